// round 15
// baseline (speedup 1.0000x reference)
#include <cuda_runtime.h>

#define E_EDGE 8192
#define BATCH  32
#define N_VAR  2048

// scratch: input transposed to [k][b] (1 MB) and llr pre-scaled+transposed to [v][b] (256 KB)
__device__ float g_inputT[E_EDGE * BATCH];
__device__ float g_llrT[N_VAR * BATCH];

__global__ __launch_bounds__(256) void prep_kernel(const float* __restrict__ input,
                                                   const float* __restrict__ llr,
                                                   const float* __restrict__ llr_w) {
    int tid = blockIdx.x * blockDim.x + threadIdx.x;
    if (tid < E_EDGE * BATCH) {
        int b = tid >> 13;           // tid / 8192  (coalesced read along k)
        int k = tid & (E_EDGE - 1);
        g_inputT[k * BATCH + b] = input[tid];
    } else {
        int t = tid - E_EDGE * BATCH;
        if (t < N_VAR * BATCH) {
            int b = t >> 11;         // t / 2048
            int v = t & (N_VAR - 1);
            g_llrT[v * BATCH + b] = llr[t] * llr_w[v];
        }
    }
}

// 256-bit streaming load (sm_100+): one instruction, one scoreboard slot, 1KB/warp.
__device__ __forceinline__ unsigned ldg256_nz(const float* p) {
    float v0, v1, v2, v3, v4, v5, v6, v7;
    asm volatile("ld.global.cs.v8.f32 {%0,%1,%2,%3,%4,%5,%6,%7}, [%8];"
                 : "=f"(v0), "=f"(v1), "=f"(v2), "=f"(v3),
                   "=f"(v4), "=f"(v5), "=f"(v6), "=f"(v7)
                 : "l"(p));
    // values die immediately into the nz word (R13 liveness trick);
    // <<1 drops sign bits so ±0.0 counts as zero (exact)
    return (__float_as_uint(v0) | __float_as_uint(v1) |
            __float_as_uint(v2) | __float_as_uint(v3) |
            __float_as_uint(v4) | __float_as_uint(v5) |
            __float_as_uint(v6) | __float_as_uint(v7)) << 1;
}

// One warp per output row e_out; lane = batch b.
// Weight is never streamed (mask*weight == 0 wherever mask == 0 for ANY weight
// values); it's gathered 32B per hit (~8 hits per row of 8192).
// R15 KEY: LDG.256 gives R4's per-warp depth (1KB via 2 loads) in 16 value regs
// and 2 scoreboard waits per KB (vs 8), at ~85% occupancy — depth AND occupancy,
// previously mutually exclusive on the LDG.128 path.
__global__ __launch_bounds__(256, 7) void bp_main_kernel(
    const float* __restrict__ mask,
    const float* __restrict__ weight,
    float* __restrict__ out)
{
    const int warp = threadIdx.x >> 5;          // 0..7
    const int lane = threadIdx.x & 31;          // batch b
    const int row0 = blockIdx.x << 3;           // 8 rows per block
    const int row  = row0 + warp;               // e_out

    const float* __restrict__ mr = mask   + (size_t)row * E_EDGE;
    const float* __restrict__ wr = weight + (size_t)row * E_EDGE;

    float acc = 0.0f;

    // 16 iterations × (2 chunks × 32 lanes × 8 floats) = 8192
    for (int it = 0; it < E_EDGE / 512; ++it) {
        const int c0 = it * 512;
        // two back-to-back 256-bit loads: 2KB per warp per iteration
        unsigned nzA = ldg256_nz(mr + c0 +       lane * 8);
        unsigned nzB = ldg256_nz(mr + c0 + 256 + lane * 8);

        #pragma unroll
        for (int half = 0; half < 2; ++half) {
            const int cbase = c0 + half * 256;
            unsigned ball = __ballot_sync(0xFFFFFFFFu, (half ? nzB : nzA) != 0u);

            // rare path: ~8 nonzeros per whole row of 8192
            while (ball) {
                int src = __ffs(ball) - 1;
                ball &= ball - 1;
                const int k0 = cbase + src * 8;
                // broadcast reloads from cache (line streamed moments ago)
                const float4 m0 = __ldg(reinterpret_cast<const float4*>(mr + k0));
                const float4 m1 = __ldg(reinterpret_cast<const float4*>(mr + k0 + 4));
                const float4 w0 = __ldg(reinterpret_cast<const float4*>(wr + k0));
                const float4 w1 = __ldg(reinterpret_cast<const float4*>(wr + k0 + 4));
                const float* t  = g_inputT + (size_t)k0 * BATCH + lane;  // coalesced
                if (m0.x != 0.0f) acc = fmaf(m0.x * w0.x, t[0 * BATCH], acc);
                if (m0.y != 0.0f) acc = fmaf(m0.y * w0.y, t[1 * BATCH], acc);
                if (m0.z != 0.0f) acc = fmaf(m0.z * w0.z, t[2 * BATCH], acc);
                if (m0.w != 0.0f) acc = fmaf(m0.w * w0.w, t[3 * BATCH], acc);
                if (m1.x != 0.0f) acc = fmaf(m1.x * w1.x, t[4 * BATCH], acc);
                if (m1.y != 0.0f) acc = fmaf(m1.y * w1.y, t[5 * BATCH], acc);
                if (m1.z != 0.0f) acc = fmaf(m1.z * w1.z, t[6 * BATCH], acc);
                if (m1.w != 0.0f) acc = fmaf(m1.w * w1.w, t[7 * BATCH], acc);
            }
        }
    }

    // epilogue: llr term (pre-scaled, coalesced) + smem transpose for full-sector stores
    __shared__ float tile[8][33];
    tile[warp][lane] = 0.5f * (g_llrT[(row & (N_VAR - 1)) * BATCH + lane] + acc);
    __syncthreads();

    // thread t: b = t>>3 (0..31), el = t&7 -> each 8-thread group writes one
    // full, aligned 32B sector of out[b][row0 .. row0+7]
    const int b  = threadIdx.x >> 3;
    const int el = threadIdx.x & 7;
    out[(size_t)b * E_EDGE + row0 + el] = tile[el][b];
}

extern "C" void kernel_launch(void* const* d_in, const int* in_sizes, int n_in,
                              void* d_out, int out_size) {
    const float* input    = (const float*)d_in[0];  // [32, 8192]
    const float* input_w  = (const float*)d_in[1];  // [8192, 8192]
    const float* mask     = (const float*)d_in[2];  // [8192, 8192]
    const float* llr      = (const float*)d_in[3];  // [32, 2048]
    const float* llr_w    = (const float*)d_in[4];  // [1, 2048]
    // d_in[5] = llr_expander (one-hot of e % N_VAR) — realized via index math
    float* out = (float*)d_out;                     // [32, 8192]

    (void)in_sizes; (void)n_in; (void)out_size;

    const int prep_n = E_EDGE * BATCH + N_VAR * BATCH;
    prep_kernel<<<(prep_n + 255) / 256, 256>>>(input, llr, llr_w);

    // 8192 rows, 8 rows (warps) per 256-thread block
    bp_main_kernel<<<E_EDGE / 8, 256>>>(mask, input_w, out);
}

// round 16
// speedup vs baseline: 1.1137x; 1.1137x over previous
#include <cuda_runtime.h>

#define E_EDGE 8192
#define BATCH  32
#define N_VAR  2048

// scratch: input transposed to [k][b] (1 MB) and llr pre-scaled+transposed to [v][b] (256 KB)
__device__ float g_inputT[E_EDGE * BATCH];
__device__ float g_llrT[N_VAR * BATCH];

// Tiled prep: blocks 0..31 transpose input (both sides coalesced via a 256x32
// smem tile, stride-33 padding -> conflict-free); blocks 32..39 build llrT.
__global__ __launch_bounds__(256) void prep_kernel(const float* __restrict__ input,
                                                   const float* __restrict__ llr,
                                                   const float* __restrict__ llr_w) {
    const int t = threadIdx.x;
    if (blockIdx.x < 32) {
        __shared__ float s[256][33];
        const int k0 = blockIdx.x * 256;
        #pragma unroll
        for (int b = 0; b < 32; ++b)
            s[t][b] = input[b * E_EDGE + k0 + t];          // coalesced 1KB reads
        __syncthreads();
        #pragma unroll
        for (int i = 0; i < 32; ++i) {
            const int o = i * 256 + t;                      // linear over (k-k0)*32+b
            g_inputT[(size_t)k0 * 32 + o] = s[o >> 5][o & 31];  // coalesced writes
        }
    } else {
        // llrT[v][b] = llr[b][v] * llr_w[v]; 8 blocks x 256 threads x 32 elems
        const int base = (blockIdx.x - 32) * 8192;
        #pragma unroll
        for (int i = 0; i < 32; ++i) {
            const int o = base + i * 256 + t;               // o = v*32 + b
            const int v = o >> 5, b = o & 31;
            g_llrT[o] = llr[b * N_VAR + v] * llr_w[v];      // writes coalesced
        }
    }
}

// One warp per output row e_out; lane = batch b.  (R4 champion config.)
// Only the mask is streamed (256 MB): mask*weight == 0 wherever mask == 0 for
// ANY weight values, so weight is gathered (one float4 per hit, ~8 hits/row).
// 8 independent 128B .cs loads per group at the 64-reg budget: best measured
// total across R3-R15; DRAM ~66% is the empirical ceiling for this pattern
// (shown invariant to occupancy 43-80%, regs 32-64, scoreboard density 1-8/KB).
__global__ __launch_bounds__(256, 4) void bp_main_kernel(
    const float* __restrict__ mask,
    const float* __restrict__ weight,
    float* __restrict__ out)
{
    const int warp = threadIdx.x >> 5;          // 0..7
    const int lane = threadIdx.x & 31;          // batch b
    const int row0 = blockIdx.x << 3;           // 8 rows per block
    const int row  = row0 + warp;               // e_out

    const float4* __restrict__ m4 = reinterpret_cast<const float4*>(mask + (size_t)row * E_EDGE);
    const float*  __restrict__ wr = weight + (size_t)row * E_EDGE;

    float acc = 0.0f;

    // 8 groups × (8 chunks × 32 lanes × 4 floats) = 8192
    for (int g = 0; g < E_EDGE / 1024; ++g) {
        float4 m[8];
        // issue all 8 mask loads back-to-back: 1 KB in flight per warp
        #pragma unroll
        for (int it = 0; it < 8; ++it)
            m[it] = __ldcs(&m4[(g * 8 + it) * 32 + lane]);

        #pragma unroll
        for (int it = 0; it < 8; ++it) {
            // integer nz test; <<1 drops sign bit so ±0.0 is skipped (exact)
            unsigned bits = (__float_as_uint(m[it].x) | __float_as_uint(m[it].y) |
                             __float_as_uint(m[it].z) | __float_as_uint(m[it].w)) << 1;
            unsigned ball = __ballot_sync(0xFFFFFFFFu, bits != 0u);

            // rare path: ~8 nonzeros per whole row of 8192
            while (ball) {
                int src = __ffs(ball) - 1;
                ball &= ball - 1;
                float mx = __shfl_sync(0xFFFFFFFFu, m[it].x, src);
                float my = __shfl_sync(0xFFFFFFFFu, m[it].y, src);
                float mz = __shfl_sync(0xFFFFFFFFu, m[it].z, src);
                float mw = __shfl_sync(0xFFFFFFFFu, m[it].w, src);
                const int k0 = (g * 8 + it) * 128 + src * 4;
                const float4 w4 = __ldg(reinterpret_cast<const float4*>(wr + k0)); // one 16B gather
                const float* t = g_inputT + (size_t)k0 * BATCH + lane;             // coalesced
                if (mx != 0.0f) acc = fmaf(mx * w4.x, t[0 * BATCH], acc);
                if (my != 0.0f) acc = fmaf(my * w4.y, t[1 * BATCH], acc);
                if (mz != 0.0f) acc = fmaf(mz * w4.z, t[2 * BATCH], acc);
                if (mw != 0.0f) acc = fmaf(mw * w4.w, t[3 * BATCH], acc);
            }
        }
    }

    // epilogue: llr term (pre-scaled, coalesced) + smem transpose for full-sector stores
    __shared__ float tile[8][33];
    const int v = row & (N_VAR - 1);
    tile[warp][lane] = 0.5f * (g_llrT[v * BATCH + lane] + acc);
    __syncthreads();

    // thread t: b = t>>3 (0..31), el = t&7 -> each 8-thread group writes one
    // full, aligned 32B sector of out[b][row0 .. row0+7]
    const int b  = threadIdx.x >> 3;
    const int el = threadIdx.x & 7;
    out[(size_t)b * E_EDGE + row0 + el] = tile[el][b];
}

extern "C" void kernel_launch(void* const* d_in, const int* in_sizes, int n_in,
                              void* d_out, int out_size) {
    const float* input    = (const float*)d_in[0];  // [32, 8192]
    const float* input_w  = (const float*)d_in[1];  // [8192, 8192]
    const float* mask     = (const float*)d_in[2];  // [8192, 8192]
    const float* llr      = (const float*)d_in[3];  // [32, 2048]
    const float* llr_w    = (const float*)d_in[4];  // [1, 2048]
    // d_in[5] = llr_expander (one-hot of e % N_VAR) — realized via index math
    float* out = (float*)d_out;                     // [32, 8192]

    (void)in_sizes; (void)n_in; (void)out_size;

    prep_kernel<<<40, 256>>>(input, llr, llr_w);

    // 8192 rows, 8 rows (warps) per 256-thread block
    bp_main_kernel<<<E_EDGE / 8, 256>>>(mask, input_w, out);
}